// round 5
// baseline (speedup 1.0000x reference)
#include <cuda_runtime.h>

#define NN 50000
#define EE 1250000
#define DD 64
#define LL 3
#define SCAN_B 256
#define NBLK ((NN + SCAN_B - 1) / SCAN_B)   // 196

// ---- scratch (static device allocations; referenced ONLY from device code) ----
__device__ float g_deg[NN];
__device__ float g_dis[NN];
__device__ float g_selfnorm[NN];
__device__ int   g_indeg[NN];
__device__ int   g_off[NN + 1];
__device__ int   g_cur[NN];
__device__ int   g_bsum[NBLK];
__device__ int   g_bpre[NBLK];
__device__ __align__(16) int2  g_edge[EE];     // {src_row, norm bits}
__device__ __align__(16) float g_x1[NN * DD];
__device__ __align__(16) float g_x2[NN * DD];

// ---------------------------------------------------------------------------
__global__ void init_k() {
    int i = blockIdx.x * blockDim.x + threadIdx.x;
    if (i < NN) { g_deg[i] = 2.0f; g_indeg[i] = 0; }
}

__global__ void deg_k(const int* __restrict__ col,
                      const float* __restrict__ w) {
    int e = blockIdx.x * blockDim.x + threadIdx.x;
    if (e < EE) {
        int c = col[e];
        atomicAdd(&g_deg[c], w[e]);
        atomicAdd(&g_indeg[c], 1);
    }
}

__global__ void dis_k() {
    int i = blockIdx.x * blockDim.x + threadIdx.x;
    if (i < NN) {
        float d = g_deg[i];              // always >= 2.0
        float s = rsqrtf(d);
        g_dis[i] = s;
        g_selfnorm[i] = 2.0f * s * s;
    }
}

// ---------------------------------------------------------------------------
// multi-block exclusive scan of indeg -> g_off / g_cur
__global__ void scan_a() {
    __shared__ int s[SCAN_B];
    int t = threadIdx.x;
    int i = blockIdx.x * SCAN_B + t;
    s[t] = (i < NN) ? g_indeg[i] : 0;
    __syncthreads();
#pragma unroll
    for (int off = SCAN_B / 2; off > 0; off >>= 1) {
        if (t < off) s[t] += s[t + off];
        __syncthreads();
    }
    if (t == 0) g_bsum[blockIdx.x] = s[0];
}

__global__ void scan_b() {
    __shared__ int s[SCAN_B];
    int t = threadIdx.x;
    s[t] = (t < NBLK) ? g_bsum[t] : 0;
    __syncthreads();
    for (int off = 1; off < SCAN_B; off <<= 1) {
        int v = (t >= off) ? s[t - off] : 0;
        __syncthreads();
        s[t] += v;
        __syncthreads();
    }
    if (t < NBLK) g_bpre[t] = (t == 0) ? 0 : s[t - 1];
    if (t == 0) g_off[NN] = EE;
}

__global__ void scan_c() {
    __shared__ int s[SCAN_B];
    int t = threadIdx.x;
    int i = blockIdx.x * SCAN_B + t;
    int v = (i < NN) ? g_indeg[i] : 0;
    s[t] = v;
    __syncthreads();
    for (int off = 1; off < SCAN_B; off <<= 1) {
        int u = (t >= off) ? s[t - off] : 0;
        __syncthreads();
        s[t] += u;
        __syncthreads();
    }
    if (i < NN) {
        int excl = s[t] - v + g_bpre[blockIdx.x];
        g_off[i] = excl;
        g_cur[i] = excl;
    }
}

// scatter edges into CSR (packed int2: row + norm)
__global__ void scatter_k(const int* __restrict__ row,
                          const int* __restrict__ col,
                          const float* __restrict__ w) {
    int e = blockIdx.x * blockDim.x + threadIdx.x;
    if (e < EE) {
        int r = row[e];
        int c = col[e];
        int p = atomicAdd(&g_cur[c], 1);
        float nrm = g_dis[r] * w[e] * g_dis[c];
        g_edge[p] = make_int2(r, __float_as_int(nrm));
    }
}

// ---------------------------------------------------------------------------
// Fused layer: y = relu( (A x) W + b ), optionally followed by out = y . Wf + bf
// One warp per node; lane holds channels {2*lane, 2*lane+1}.
// src: 0=xin, 1=g_x1, 2=g_x2.  mode 0: write float2 rows to dst (1=g_x1,2=g_x2)
// mode 1: final projection to out.
__global__ void __launch_bounds__(256) fused_k(const float* __restrict__ xin,
                                               int src,
                                               const float* __restrict__ W,
                                               const float* __restrict__ bias,
                                               int dst, int mode,
                                               const float* __restrict__ Wf,
                                               const float* __restrict__ bf,
                                               float* __restrict__ out) {
    const float* X = (src == 0) ? xin : ((src == 1) ? g_x1 : g_x2);

    __shared__ float ws[64][64];           // W[k][c]
    int tid = threadIdx.x;
    {
        const float4* W4 = (const float4*)W;
        float4* ws4 = (float4*)&ws[0][0];
#pragma unroll
        for (int i = 0; i < 4; ++i) ws4[tid + i * 256] = W4[tid + i * 256];
    }
    __syncthreads();

    int node = blockIdx.x * 8 + (tid >> 5);    // grid = NN/8 exactly
    int lane = tid & 31;

    // ---- gather-aggregate: a = (A x)[node], float2 per lane ----
    const float2* X2 = (const float2*)X;
    float sn = g_selfnorm[node];
    float2 hv = X2[node * 32 + lane];
    float ax = hv.x * sn, ay = hv.y * sn;

    int p = g_off[node], e = g_off[node + 1];
    for (; p + 1 < e; p += 2) {
        int2 e1 = g_edge[p];
        int2 e2 = g_edge[p + 1];
        float n1 = __int_as_float(e1.y);
        float n2 = __int_as_float(e2.y);
        float2 a = X2[e1.x * 32 + lane];
        float2 b = X2[e2.x * 32 + lane];
        ax += a.x * n1 + b.x * n2;
        ay += a.y * n1 + b.y * n2;
    }
    if (p < e) {
        int2 e1 = g_edge[p];
        float n1 = __int_as_float(e1.y);
        float2 a = X2[e1.x * 32 + lane];
        ax += a.x * n1;
        ay += a.y * n1;
    }

    // ---- epilogue: o = a @ W  (a distributed across warp) ----
    float o0 = 0.f, o1 = 0.f;
#pragma unroll
    for (int k = 0; k < 64; k += 2) {
        float akx = __shfl_sync(0xffffffffu, ax, k >> 1);
        float aky = __shfl_sync(0xffffffffu, ay, k >> 1);
        float2 w0 = *(const float2*)&ws[k    ][lane * 2];
        float2 w1 = *(const float2*)&ws[k + 1][lane * 2];
        o0 += akx * w0.x + aky * w1.x;
        o1 += akx * w0.y + aky * w1.y;
    }
    o0 = fmaxf(o0 + bias[lane * 2    ], 0.f);
    o1 = fmaxf(o1 + bias[lane * 2 + 1], 0.f);

    if (mode == 0) {
        float2* Y = (float2*)((dst == 1) ? g_x1 : g_x2);
        Y[node * 32 + lane] = make_float2(o0, o1);
    } else {
        // fused final projection: out[node] = y . Wf + bf
        float a = o0 * Wf[lane * 2] + o1 * Wf[lane * 2 + 1];
#pragma unroll
        for (int o = 16; o; o >>= 1) a += __shfl_down_sync(0xffffffffu, a, o);
        if (lane == 0) out[node] = a + bf[0];
    }
}

// ---------------------------------------------------------------------------
extern "C" void kernel_launch(void* const* d_in, const int* in_sizes, int n_in,
                              void* d_out, int out_size) {
    const float* x  = (const float*)d_in[0];
    const int*   ei = (const int*)d_in[1];      // [2, E] (int32 on device)
    const float* ew = (const float*)d_in[2];
    const float* Ws = (const float*)d_in[3];    // [L, 64, 64]
    const float* bs = (const float*)d_in[4];    // [L, 64]
    const float* Wf = (const float*)d_in[5];    // [64, 1]
    const float* bf = (const float*)d_in[6];    // [1]
    float*       out = (float*)d_out;
    // d_in[7] = prob (unused, dropout p=0)

    const int* erow = ei;        // sources (x_j)
    const int* ecol = ei + EE;   // targets (aggregation)

    const int TB = 256;
    // graph normalization + CSR build (once, reused by all layers)
    init_k   <<<(NN + TB - 1) / TB, TB>>>();
    deg_k    <<<(EE + TB - 1) / TB, TB>>>(ecol, ew);
    dis_k    <<<(NN + TB - 1) / TB, TB>>>();
    scan_a   <<<NBLK, SCAN_B>>>();
    scan_b   <<<1, SCAN_B>>>();
    scan_c   <<<NBLK, SCAN_B>>>();
    scatter_k<<<(EE + TB - 1) / TB, TB>>>(erow, ecol, ew);

    // layer 0: x -> g_x1
    fused_k<<<NN / 8, 256>>>(x, 0, Ws + 0 * DD * DD, bs + 0 * DD, 1, 0, Wf, bf, out);
    // layer 1: g_x1 -> g_x2
    fused_k<<<NN / 8, 256>>>(x, 1, Ws + 1 * DD * DD, bs + 1 * DD, 2, 0, Wf, bf, out);
    // layer 2 + final projection: g_x2 -> out
    fused_k<<<NN / 8, 256>>>(x, 2, Ws + 2 * DD * DD, bs + 2 * DD, 0, 1, Wf, bf, out);
}

// round 6
// speedup vs baseline: 1.2096x; 1.2096x over previous
#include <cuda_runtime.h>

#define NN 50000
#define EE 1250000
#define DD 64
#define LL 3
#define SCAN_B 256
#define NBLK ((NN + SCAN_B - 1) / SCAN_B)   // 196

// ---- scratch (static device allocations; referenced ONLY from device code) ----
__device__ float g_deg[NN];
__device__ float g_dis[NN];
__device__ float g_selfnorm[NN];
__device__ int   g_indeg[NN];
__device__ int   g_off[NN + 1];
__device__ int   g_cur[NN];
__device__ int   g_bsum[NBLK];
__device__ int   g_bpre[NBLK];
__device__ __align__(16) int2  g_edge[EE];     // {src_row, norm bits}
__device__ __align__(16) float g_h [NN * DD];
__device__ __align__(16) float g_x1[NN * DD];
__device__ __align__(16) float g_x2[NN * DD];

// ---------------------------------------------------------------------------
__global__ void init_k() {
    int i = blockIdx.x * blockDim.x + threadIdx.x;
    if (i < NN) { g_deg[i] = 2.0f; g_indeg[i] = 0; }
}

__global__ void deg_k(const int* __restrict__ col,
                      const float* __restrict__ w) {
    int e = blockIdx.x * blockDim.x + threadIdx.x;
    if (e < EE) {
        int c = col[e];
        atomicAdd(&g_deg[c], w[e]);
        atomicAdd(&g_indeg[c], 1);
    }
}

// ---------------------------------------------------------------------------
// dis/selfnorm + per-block indeg sums (merged; both need only deg/indeg)
__global__ void dis_scan_a() {
    __shared__ int s[SCAN_B];
    int t = threadIdx.x;
    int i = blockIdx.x * SCAN_B + t;
    int v = 0;
    if (i < NN) {
        float d = g_deg[i];              // always >= 2.0
        float sc = rsqrtf(d);
        g_dis[i] = sc;
        g_selfnorm[i] = 2.0f * sc * sc;
        v = g_indeg[i];
    }
    s[t] = v;
    __syncthreads();
#pragma unroll
    for (int off = SCAN_B / 2; off > 0; off >>= 1) {
        if (t < off) s[t] += s[t + off];
        __syncthreads();
    }
    if (t == 0) g_bsum[blockIdx.x] = s[0];
}

__global__ void scan_b() {
    __shared__ int s[SCAN_B];
    int t = threadIdx.x;
    s[t] = (t < NBLK) ? g_bsum[t] : 0;
    __syncthreads();
    for (int off = 1; off < SCAN_B; off <<= 1) {
        int v = (t >= off) ? s[t - off] : 0;
        __syncthreads();
        s[t] += v;
        __syncthreads();
    }
    if (t < NBLK) g_bpre[t] = (t == 0) ? 0 : s[t - 1];
    if (t == 0) g_off[NN] = EE;
}

__global__ void scan_c() {
    __shared__ int s[SCAN_B];
    int t = threadIdx.x;
    int i = blockIdx.x * SCAN_B + t;
    int v = (i < NN) ? g_indeg[i] : 0;
    s[t] = v;
    __syncthreads();
    for (int off = 1; off < SCAN_B; off <<= 1) {
        int u = (t >= off) ? s[t - off] : 0;
        __syncthreads();
        s[t] += u;
        __syncthreads();
    }
    if (i < NN) {
        int excl = s[t] - v + g_bpre[blockIdx.x];
        g_off[i] = excl;
        g_cur[i] = excl;
    }
}

// scatter edges into CSR (packed int2: row + norm), one ST.64 per edge
__global__ void scatter_k(const int* __restrict__ row,
                          const int* __restrict__ col,
                          const float* __restrict__ w) {
    int e = blockIdx.x * blockDim.x + threadIdx.x;
    if (e < EE) {
        int r = row[e];
        int c = col[e];
        int p = atomicAdd(&g_cur[c], 1);
        float nrm = g_dis[r] * w[e] * g_dis[c];
        g_edge[p] = make_int2(r, __float_as_int(nrm));
    }
}

// ---------------------------------------------------------------------------
// H = X @ W   (50000 x 64 @ 64 x 64). src selector: 0=x(input), 1=g_x1, 2=g_x2
__global__ void __launch_bounds__(256) gemm_k(const float* __restrict__ xin,
                                              int src,
                                              const float* __restrict__ W) {
    const float* X = (src == 0) ? xin : ((src == 1) ? g_x1 : g_x2);

    __shared__ float xsT[64][64];   // xsT[k][r] (transposed tile)
    __shared__ float ws [64][64];   // ws[k][c]
    int tid = threadIdx.x;
    int rbase = blockIdx.x * 64;

    const float4* W4 = (const float4*)W;
    float4* ws4 = (float4*)&ws[0][0];
#pragma unroll
    for (int i = 0; i < 4; ++i) ws4[tid + i * 256] = W4[tid + i * 256];

    const float4* X4 = (const float4*)X;
#pragma unroll
    for (int i = 0; i < 4; ++i) {
        int idx4 = tid + i * 256;        // 0..1023 float4 of the 64x64 tile
        int r  = idx4 >> 4;              // 0..63
        int q  = idx4 & 15;              // float4 column group
        int gr = rbase + r;
        float4 v = (gr < NN) ? X4[gr * 16 + q] : make_float4(0.f, 0.f, 0.f, 0.f);
        int k0 = q << 2;
        xsT[k0    ][r] = v.x;
        xsT[k0 + 1][r] = v.y;
        xsT[k0 + 2][r] = v.z;
        xsT[k0 + 3][r] = v.w;
    }
    __syncthreads();

    int tx = tid & 15, ty = tid >> 4;
    int r0 = ty * 4, c0 = tx * 4;
    float acc[4][4] = {};
#pragma unroll
    for (int k = 0; k < 64; ++k) {
        float4 xv = *(const float4*)&xsT[k][r0];
        float4 wv = *(const float4*)&ws[k][c0];
        acc[0][0] += xv.x * wv.x; acc[0][1] += xv.x * wv.y; acc[0][2] += xv.x * wv.z; acc[0][3] += xv.x * wv.w;
        acc[1][0] += xv.y * wv.x; acc[1][1] += xv.y * wv.y; acc[1][2] += xv.y * wv.z; acc[1][3] += xv.y * wv.w;
        acc[2][0] += xv.z * wv.x; acc[2][1] += xv.z * wv.y; acc[2][2] += xv.z * wv.z; acc[2][3] += xv.z * wv.w;
        acc[3][0] += xv.w * wv.x; acc[3][1] += xv.w * wv.y; acc[3][2] += xv.w * wv.z; acc[3][3] += xv.w * wv.w;
    }

    float4* H4 = (float4*)g_h;
#pragma unroll
    for (int i = 0; i < 4; ++i) {
        int gr = rbase + r0 + i;
        if (gr < NN) {
            float4 o = make_float4(acc[i][0], acc[i][1], acc[i][2], acc[i][3]);
            H4[gr * 16 + (c0 >> 2)] = o;
        }
    }
}

// ---------------------------------------------------------------------------
// gather-aggregate: one warp per node, float2 per lane, relu(agg + b).
// mode 0: write to dst (1=g_x1, 2=g_x2). mode 1: fused final projection to out.
__global__ void __launch_bounds__(256) agg_k(const float* __restrict__ bias,
                                             int dst, int mode,
                                             const float* __restrict__ Wf,
                                             const float* __restrict__ bf,
                                             float* __restrict__ out) {
    int node = blockIdx.x * 8 + (threadIdx.x >> 5);   // grid = NN/8 exactly
    int lane = threadIdx.x & 31;

    const float2* H2 = (const float2*)g_h;
    float sn = g_selfnorm[node];
    float2 hv = H2[node * 32 + lane];
    float ax = hv.x * sn, ay = hv.y * sn;

    int p = g_off[node], e = g_off[node + 1];
    for (; p + 3 < e; p += 4) {
        int2 e1 = g_edge[p];
        int2 e2 = g_edge[p + 1];
        int2 e3 = g_edge[p + 2];
        int2 e4 = g_edge[p + 3];
        float2 a = H2[e1.x * 32 + lane];
        float2 b = H2[e2.x * 32 + lane];
        float2 c = H2[e3.x * 32 + lane];
        float2 d = H2[e4.x * 32 + lane];
        float n1 = __int_as_float(e1.y), n2 = __int_as_float(e2.y);
        float n3 = __int_as_float(e3.y), n4 = __int_as_float(e4.y);
        ax += a.x * n1 + b.x * n2 + c.x * n3 + d.x * n4;
        ay += a.y * n1 + b.y * n2 + c.y * n3 + d.y * n4;
    }
    for (; p < e; ++p) {
        int2 e1 = g_edge[p];
        float n1 = __int_as_float(e1.y);
        float2 a = H2[e1.x * 32 + lane];
        ax += a.x * n1;
        ay += a.y * n1;
    }

    float o0 = fmaxf(ax + bias[lane * 2    ], 0.f);
    float o1 = fmaxf(ay + bias[lane * 2 + 1], 0.f);

    if (mode == 0) {
        float2* Y = (float2*)((dst == 1) ? g_x1 : g_x2);
        Y[node * 32 + lane] = make_float2(o0, o1);
    } else {
        float a = o0 * Wf[lane * 2] + o1 * Wf[lane * 2 + 1];
#pragma unroll
        for (int o = 16; o; o >>= 1) a += __shfl_down_sync(0xffffffffu, a, o);
        if (lane == 0) out[node] = a + bf[0];
    }
}

// ---------------------------------------------------------------------------
extern "C" void kernel_launch(void* const* d_in, const int* in_sizes, int n_in,
                              void* d_out, int out_size) {
    const float* x  = (const float*)d_in[0];
    const int*   ei = (const int*)d_in[1];      // [2, E] (int32 on device)
    const float* ew = (const float*)d_in[2];
    const float* Ws = (const float*)d_in[3];    // [L, 64, 64]
    const float* bs = (const float*)d_in[4];    // [L, 64]
    const float* Wf = (const float*)d_in[5];    // [64, 1]
    const float* bf = (const float*)d_in[6];    // [1]
    float*       out = (float*)d_out;
    // d_in[7] = prob (unused, dropout p=0)

    const int* erow = ei;        // sources (x_j)
    const int* ecol = ei + EE;   // targets (aggregation)

    const int TB = 256;
    // graph normalization + CSR build (once, reused by all layers)
    init_k    <<<(NN + TB - 1) / TB, TB>>>();
    deg_k     <<<(EE + TB - 1) / TB, TB>>>(ecol, ew);
    dis_scan_a<<<NBLK, SCAN_B>>>();
    scan_b    <<<1, SCAN_B>>>();
    scan_c    <<<NBLK, SCAN_B>>>();
    scatter_k <<<(EE + TB - 1) / TB, TB>>>(erow, ecol, ew);

    // layer 0: x -> g_h -> g_x1
    gemm_k<<<(NN + 63) / 64, 256>>>(x, 0, Ws + 0 * DD * DD);
    agg_k <<<NN / 8, 256>>>(bs + 0 * DD, 1, 0, Wf, bf, out);
    // layer 1: g_x1 -> g_h -> g_x2
    gemm_k<<<(NN + 63) / 64, 256>>>(x, 1, Ws + 1 * DD * DD);
    agg_k <<<NN / 8, 256>>>(bs + 1 * DD, 2, 0, Wf, bf, out);
    // layer 2: g_x2 -> g_h -> out (fused final projection)
    gemm_k<<<(NN + 63) / 64, 256>>>(x, 2, Ws + 2 * DD * DD);
    agg_k <<<NN / 8, 256>>>(bs + 2 * DD, 0, 1, Wf, bf, out);
}

// round 7
// speedup vs baseline: 1.3627x; 1.1265x over previous
#include <cuda_runtime.h>
#include <cuda_fp16.h>

#define NN 50000
#define EE 1250000
#define DD 64
#define LL 3
#define SCAN_B 256
#define NBLK ((NN + SCAN_B - 1) / SCAN_B)   // 196

// ---- scratch (static device allocations; referenced ONLY from device code) ----
__device__ float g_deg[NN];
__device__ float g_dis[NN];
__device__ float g_selfnorm[NN];
__device__ int   g_indeg[NN];
__device__ int   g_off[NN + 1];
__device__ int   g_cur[NN];
__device__ int   g_bsum[NBLK];
__device__ __align__(16) int2    g_edge[EE];      // {src_row, norm bits}
__device__ __align__(16) __half2 g_h2[NN * 32];   // H in fp16 (gather payload)
__device__ __align__(16) float   g_x1[NN * DD];
__device__ __align__(16) float   g_x2[NN * DD];

// ---------------------------------------------------------------------------
__global__ void init_k() {
    int i = blockIdx.x * blockDim.x + threadIdx.x;
    if (i < NN) { g_deg[i] = 2.0f; g_indeg[i] = 0; }
}

__global__ void deg_k(const int* __restrict__ col,
                      const float* __restrict__ w) {
    int e = blockIdx.x * blockDim.x + threadIdx.x;
    if (e < EE) {
        int c = col[e];
        atomicAdd(&g_deg[c], w[e]);
        atomicAdd(&g_indeg[c], 1);
    }
}

// ---------------------------------------------------------------------------
// dis/selfnorm + per-block indeg sums (merged)
__global__ void dis_scan_a() {
    __shared__ int s[SCAN_B];
    int t = threadIdx.x;
    int i = blockIdx.x * SCAN_B + t;
    int v = 0;
    if (i < NN) {
        float d = g_deg[i];              // always >= 2.0
        float sc = rsqrtf(d);
        g_dis[i] = sc;
        g_selfnorm[i] = 2.0f * sc * sc;
        v = g_indeg[i];
    }
    s[t] = v;
    __syncthreads();
#pragma unroll
    for (int off = SCAN_B / 2; off > 0; off >>= 1) {
        if (t < off) s[t] += s[t + off];
        __syncthreads();
    }
    if (t == 0) g_bsum[blockIdx.x] = s[0];
}

// per-block exclusive scan; block prefix computed inline from g_bsum
__global__ void scan_c() {
    __shared__ int s[SCAN_B];
    __shared__ int bpre;
    int t = threadIdx.x;

    // block prefix = sum of g_bsum[0 .. blockIdx.x)
    int pv = (t < NBLK && t < blockIdx.x) ? g_bsum[t] : 0;
    s[t] = pv;
    __syncthreads();
#pragma unroll
    for (int off = SCAN_B / 2; off > 0; off >>= 1) {
        if (t < off) s[t] += s[t + off];
        __syncthreads();
    }
    if (t == 0) bpre = s[0];
    __syncthreads();

    int i = blockIdx.x * SCAN_B + t;
    int v = (i < NN) ? g_indeg[i] : 0;
    s[t] = v;
    __syncthreads();
    for (int off = 1; off < SCAN_B; off <<= 1) {
        int u = (t >= off) ? s[t - off] : 0;
        __syncthreads();
        s[t] += u;
        __syncthreads();
    }
    if (i < NN) {
        int excl = s[t] - v + bpre;
        g_off[i] = excl;
        g_cur[i] = excl;
    }
    if (blockIdx.x == 0 && t == 0) g_off[NN] = EE;
}

// scatter edges into CSR (packed int2: row + norm), one ST.64 per edge
__global__ void scatter_k(const int* __restrict__ row,
                          const int* __restrict__ col,
                          const float* __restrict__ w) {
    int e = blockIdx.x * blockDim.x + threadIdx.x;
    if (e < EE) {
        int r = row[e];
        int c = col[e];
        int p = atomicAdd(&g_cur[c], 1);
        float nrm = g_dis[r] * w[e] * g_dis[c];
        g_edge[p] = make_int2(r, __float_as_int(nrm));
    }
}

// ---------------------------------------------------------------------------
// H = X @ W   (fp32 compute, fp16 output). src: 0=x(input), 1=g_x1, 2=g_x2
__global__ void __launch_bounds__(256) gemm_k(const float* __restrict__ xin,
                                              int src,
                                              const float* __restrict__ W) {
    const float* X = (src == 0) ? xin : ((src == 1) ? g_x1 : g_x2);

    __shared__ float xsT[64][64];   // xsT[k][r] (transposed tile)
    __shared__ float ws [64][64];   // ws[k][c]
    int tid = threadIdx.x;
    int rbase = blockIdx.x * 64;

    const float4* W4 = (const float4*)W;
    float4* ws4 = (float4*)&ws[0][0];
#pragma unroll
    for (int i = 0; i < 4; ++i) ws4[tid + i * 256] = W4[tid + i * 256];

    const float4* X4 = (const float4*)X;
#pragma unroll
    for (int i = 0; i < 4; ++i) {
        int idx4 = tid + i * 256;        // 0..1023 float4 of the 64x64 tile
        int r  = idx4 >> 4;              // 0..63
        int q  = idx4 & 15;              // float4 column group
        int gr = rbase + r;
        float4 v = (gr < NN) ? X4[gr * 16 + q] : make_float4(0.f, 0.f, 0.f, 0.f);
        int k0 = q << 2;
        xsT[k0    ][r] = v.x;
        xsT[k0 + 1][r] = v.y;
        xsT[k0 + 2][r] = v.z;
        xsT[k0 + 3][r] = v.w;
    }
    __syncthreads();

    int tx = tid & 15, ty = tid >> 4;
    int r0 = ty * 4, c0 = tx * 4;
    float acc[4][4] = {};
#pragma unroll
    for (int k = 0; k < 64; ++k) {
        float4 xv = *(const float4*)&xsT[k][r0];
        float4 wv = *(const float4*)&ws[k][c0];
        acc[0][0] += xv.x * wv.x; acc[0][1] += xv.x * wv.y; acc[0][2] += xv.x * wv.z; acc[0][3] += xv.x * wv.w;
        acc[1][0] += xv.y * wv.x; acc[1][1] += xv.y * wv.y; acc[1][2] += xv.y * wv.z; acc[1][3] += xv.y * wv.w;
        acc[2][0] += xv.z * wv.x; acc[2][1] += xv.z * wv.y; acc[2][2] += xv.z * wv.z; acc[2][3] += xv.z * wv.w;
        acc[3][0] += xv.w * wv.x; acc[3][1] += xv.w * wv.y; acc[3][2] += xv.w * wv.z; acc[3][3] += xv.w * wv.w;
    }

#pragma unroll
    for (int i = 0; i < 4; ++i) {
        int gr = rbase + r0 + i;
        if (gr < NN) {
            __half2 h0 = __floats2half2_rn(acc[i][0], acc[i][1]);
            __half2 h1 = __floats2half2_rn(acc[i][2], acc[i][3]);
            uint2 pk = make_uint2(*(unsigned*)&h0, *(unsigned*)&h1);
            *(uint2*)(g_h2 + gr * 32 + (c0 >> 1)) = pk;   // 8B-aligned (c0 % 4 == 0)
        }
    }
}

// ---------------------------------------------------------------------------
// gather-aggregate (fp16 rows, fp32 accumulate): one warp per node.
// mode 0: write to dst (1=g_x1, 2=g_x2). mode 1: fused final projection to out.
__global__ void __launch_bounds__(256) agg_k(const float* __restrict__ bias,
                                             int dst, int mode,
                                             const float* __restrict__ Wf,
                                             const float* __restrict__ bf,
                                             float* __restrict__ out) {
    int node = blockIdx.x * 8 + (threadIdx.x >> 5);   // grid = NN/8 exactly
    int lane = threadIdx.x & 31;

    const __half2* H2 = g_h2;
    float sn = g_selfnorm[node];
    float2 hv = __half22float2(H2[node * 32 + lane]);
    float ax = hv.x * sn, ay = hv.y * sn;

    int p = g_off[node], e = g_off[node + 1];
    for (; p + 3 < e; p += 4) {
        int2 e1 = g_edge[p];
        int2 e2 = g_edge[p + 1];
        int2 e3 = g_edge[p + 2];
        int2 e4 = g_edge[p + 3];
        float2 a = __half22float2(H2[e1.x * 32 + lane]);
        float2 b = __half22float2(H2[e2.x * 32 + lane]);
        float2 c = __half22float2(H2[e3.x * 32 + lane]);
        float2 d = __half22float2(H2[e4.x * 32 + lane]);
        float n1 = __int_as_float(e1.y), n2 = __int_as_float(e2.y);
        float n3 = __int_as_float(e3.y), n4 = __int_as_float(e4.y);
        ax += a.x * n1 + b.x * n2 + c.x * n3 + d.x * n4;
        ay += a.y * n1 + b.y * n2 + c.y * n3 + d.y * n4;
    }
    for (; p < e; ++p) {
        int2 e1 = g_edge[p];
        float n1 = __int_as_float(e1.y);
        float2 a = __half22float2(H2[e1.x * 32 + lane]);
        ax += a.x * n1;
        ay += a.y * n1;
    }

    float o0 = fmaxf(ax + bias[lane * 2    ], 0.f);
    float o1 = fmaxf(ay + bias[lane * 2 + 1], 0.f);

    if (mode == 0) {
        float2* Y = (float2*)((dst == 1) ? g_x1 : g_x2);
        Y[node * 32 + lane] = make_float2(o0, o1);
    } else {
        float a = o0 * Wf[lane * 2] + o1 * Wf[lane * 2 + 1];
#pragma unroll
        for (int o = 16; o; o >>= 1) a += __shfl_down_sync(0xffffffffu, a, o);
        if (lane == 0) out[node] = a + bf[0];
    }
}

// ---------------------------------------------------------------------------
extern "C" void kernel_launch(void* const* d_in, const int* in_sizes, int n_in,
                              void* d_out, int out_size) {
    const float* x  = (const float*)d_in[0];
    const int*   ei = (const int*)d_in[1];      // [2, E] (int32 on device)
    const float* ew = (const float*)d_in[2];
    const float* Ws = (const float*)d_in[3];    // [L, 64, 64]
    const float* bs = (const float*)d_in[4];    // [L, 64]
    const float* Wf = (const float*)d_in[5];    // [64, 1]
    const float* bf = (const float*)d_in[6];    // [1]
    float*       out = (float*)d_out;
    // d_in[7] = prob (unused, dropout p=0)

    const int* erow = ei;        // sources (x_j)
    const int* ecol = ei + EE;   // targets (aggregation)

    const int TB = 256;
    // graph normalization + CSR build (once, reused by all layers)
    init_k    <<<(NN + TB - 1) / TB, TB>>>();
    deg_k     <<<(EE + TB - 1) / TB, TB>>>(ecol, ew);
    dis_scan_a<<<NBLK, SCAN_B>>>();
    scan_c    <<<NBLK, SCAN_B>>>();
    scatter_k <<<(EE + TB - 1) / TB, TB>>>(erow, ecol, ew);

    // layer 0: x -> g_h2 -> g_x1
    gemm_k<<<(NN + 63) / 64, 256>>>(x, 0, Ws + 0 * DD * DD);
    agg_k <<<NN / 8, 256>>>(bs + 0 * DD, 1, 0, Wf, bf, out);
    // layer 1: g_x1 -> g_h2 -> g_x2
    gemm_k<<<(NN + 63) / 64, 256>>>(x, 1, Ws + 1 * DD * DD);
    agg_k <<<NN / 8, 256>>>(bs + 1 * DD, 2, 0, Wf, bf, out);
    // layer 2: g_x2 -> g_h2 -> out (fused final projection)
    gemm_k<<<(NN + 63) / 64, 256>>>(x, 2, Ws + 2 * DD * DD);
    agg_k <<<NN / 8, 256>>>(bs + 2 * DD, 0, 1, Wf, bf, out);
}

// round 8
// speedup vs baseline: 1.6870x; 1.2380x over previous
#include <cuda_runtime.h>
#include <cuda_fp16.h>

#define NN 50000
#define EE 1250000
#define DD 64
#define LL 3
#define SCAN_B 256
#define NBLK ((NN + SCAN_B - 1) / SCAN_B)   // 196

// ---- scratch (static device allocations; referenced ONLY from device code) ----
__device__ float g_deg[NN];
__device__ float g_dis[NN];
__device__ float g_selfnorm[NN];
__device__ int   g_indeg[NN];
__device__ int   g_off[NN + 1];
__device__ int   g_cur[NN];
__device__ int   g_bsum[NBLK];
__device__ __align__(16) int2    g_edge[EE];       // {src_row, norm bits}
__device__ __align__(16) __half2 g_h2 [NN * 32];   // H  (fp16, gather payload)
__device__ __align__(16) __half2 g_xh1[NN * 32];   // activations fp16
__device__ __align__(16) __half2 g_xh2[NN * 32];

__device__ __forceinline__ unsigned sa(const void* p) {
    return (unsigned)__cvta_generic_to_shared(p);
}

// ---------------------------------------------------------------------------
__global__ void init_k() {
    int i = blockIdx.x * blockDim.x + threadIdx.x;
    if (i < NN) { g_deg[i] = 2.0f; g_indeg[i] = 0; }
}

// 4 edges per thread, vectorized reads
__global__ void deg_k(const int* __restrict__ col,
                      const float* __restrict__ w) {
    int i = blockIdx.x * blockDim.x + threadIdx.x;   // i < EE/4
    if (i < EE / 4) {
        int4   c4 = ((const int4*)col)[i];
        float4 w4 = ((const float4*)w)[i];
        atomicAdd(&g_deg[c4.x], w4.x); atomicAdd(&g_indeg[c4.x], 1);
        atomicAdd(&g_deg[c4.y], w4.y); atomicAdd(&g_indeg[c4.y], 1);
        atomicAdd(&g_deg[c4.z], w4.z); atomicAdd(&g_indeg[c4.z], 1);
        atomicAdd(&g_deg[c4.w], w4.w); atomicAdd(&g_indeg[c4.w], 1);
    }
}

// dis/selfnorm + per-block indeg sums (merged)
__global__ void dis_scan_a() {
    __shared__ int s[SCAN_B];
    int t = threadIdx.x;
    int i = blockIdx.x * SCAN_B + t;
    int v = 0;
    if (i < NN) {
        float d = g_deg[i];              // always >= 2.0
        float sc = rsqrtf(d);
        g_dis[i] = sc;
        g_selfnorm[i] = 2.0f * sc * sc;
        v = g_indeg[i];
    }
    s[t] = v;
    __syncthreads();
#pragma unroll
    for (int off = SCAN_B / 2; off > 0; off >>= 1) {
        if (t < off) s[t] += s[t + off];
        __syncthreads();
    }
    if (t == 0) g_bsum[blockIdx.x] = s[0];
}

// per-block exclusive scan; block prefix computed inline from g_bsum
__global__ void scan_c() {
    __shared__ int s[SCAN_B];
    __shared__ int bpre;
    int t = threadIdx.x;

    int pv = (t < NBLK && t < blockIdx.x) ? g_bsum[t] : 0;
    s[t] = pv;
    __syncthreads();
#pragma unroll
    for (int off = SCAN_B / 2; off > 0; off >>= 1) {
        if (t < off) s[t] += s[t + off];
        __syncthreads();
    }
    if (t == 0) bpre = s[0];
    __syncthreads();

    int i = blockIdx.x * SCAN_B + t;
    int v = (i < NN) ? g_indeg[i] : 0;
    s[t] = v;
    __syncthreads();
    for (int off = 1; off < SCAN_B; off <<= 1) {
        int u = (t >= off) ? s[t - off] : 0;
        __syncthreads();
        s[t] += u;
        __syncthreads();
    }
    if (i < NN) {
        int excl = s[t] - v + bpre;
        g_off[i] = excl;
        g_cur[i] = excl;
    }
    if (blockIdx.x == 0 && t == 0) g_off[NN] = EE;
}

// scatter 4 edges per thread (vectorized reads, one ST.64 per edge)
__global__ void scatter_k(const int* __restrict__ row,
                          const int* __restrict__ col,
                          const float* __restrict__ w) {
    int i = blockIdx.x * blockDim.x + threadIdx.x;
    if (i < EE / 4) {
        int4   r4 = ((const int4*)row)[i];
        int4   c4 = ((const int4*)col)[i];
        float4 w4 = ((const float4*)w)[i];
        int p;
        p = atomicAdd(&g_cur[c4.x], 1);
        g_edge[p] = make_int2(r4.x, __float_as_int(g_dis[r4.x] * w4.x * g_dis[c4.x]));
        p = atomicAdd(&g_cur[c4.y], 1);
        g_edge[p] = make_int2(r4.y, __float_as_int(g_dis[r4.y] * w4.y * g_dis[c4.y]));
        p = atomicAdd(&g_cur[c4.z], 1);
        g_edge[p] = make_int2(r4.z, __float_as_int(g_dis[r4.z] * w4.z * g_dis[c4.z]));
        p = atomicAdd(&g_cur[c4.w], 1);
        g_edge[p] = make_int2(r4.w, __float_as_int(g_dis[r4.w] * w4.w * g_dis[c4.w]));
    }
}

// ---------------------------------------------------------------------------
// H = X @ W, fp16 tensor-core GEMM (mma.sync m16n8k16, fp32 accum, fp16 out).
// CTA: 64 rows x 64 cols, K=64. 8 warps: warp_m = wid%4 (16 rows), warp_n = wid/4 (32 cols).
// src: 0 = fp32 xin, 1 = g_xh1, 2 = g_xh2.
__global__ void __launch_bounds__(256) gemm_k(const float* __restrict__ xin,
                                              int src,
                                              const float* __restrict__ W) {
    __shared__ __half xs[64][72];   // X tile  (pad 72: row 144B, 16B-aligned)
    __shared__ __half ws[64][72];   // W[k][n]
    int tid = threadIdx.x;
    int rbase = blockIdx.x * 64;

    // stage W: fp32 -> fp16 (4096 elems, 16/thread via float4)
    {
        const float4* W4 = (const float4*)W;
#pragma unroll
        for (int i = 0; i < 4; ++i) {
            int idx4 = tid + i * 256;          // 0..1023
            int r = idx4 >> 4, q = idx4 & 15;  // row, float4-group
            float4 v = W4[idx4];
            __half2 h0 = __floats2half2_rn(v.x, v.y);
            __half2 h1 = __floats2half2_rn(v.z, v.w);
            *(__half2*)&ws[r][q * 4]     = h0;
            *(__half2*)&ws[r][q * 4 + 2] = h1;
        }
    }

    // stage X tile
    if (src == 0) {
        const float4* X4 = (const float4*)xin;
#pragma unroll
        for (int i = 0; i < 4; ++i) {
            int idx4 = tid + i * 256;
            int r = idx4 >> 4, q = idx4 & 15;
            int gr = rbase + r;
            float4 v = (gr < NN) ? X4[gr * 16 + q] : make_float4(0.f, 0.f, 0.f, 0.f);
            __half2 h0 = __floats2half2_rn(v.x, v.y);
            __half2 h1 = __floats2half2_rn(v.z, v.w);
            *(__half2*)&xs[r][q * 4]     = h0;
            *(__half2*)&xs[r][q * 4 + 2] = h1;
        }
    } else {
        const uint4* Xh = (const uint4*)((src == 1) ? g_xh1 : g_xh2); // 8 uint4 per row
#pragma unroll
        for (int i = 0; i < 2; ++i) {
            int idx = tid + i * 256;           // 0..511
            int r = idx >> 3, q = idx & 7;
            int gr = rbase + r;
            uint4 v = (gr < NN) ? Xh[gr * 8 + q] : make_uint4(0u, 0u, 0u, 0u);
            *(uint4*)&xs[r][q * 8] = v;
        }
    }
    __syncthreads();

    int wid  = tid >> 5, lane = tid & 31;
    int m0 = (wid & 3) * 16;          // warp row base
    int n0 = (wid >> 2) * 32;         // warp col base

    float c[4][4] = {};               // 4 n8-tiles x 4 accum regs

    // A-frag lane address: rows m0 + (lane&15), col = kk*16 + (lane>>4)*8
    // B-frag (x4.trans): row = kk*16 + (lane&7) + ((lane>>3)&1)*8, col = nb + (lane>>4)*8
#pragma unroll
    for (int kk = 0; kk < 4; ++kk) {
        unsigned a0, a1, a2, a3;
        {
            unsigned addr = sa(&xs[m0 + (lane & 15)][kk * 16 + (lane >> 4) * 8]);
            asm volatile("ldmatrix.sync.aligned.m8n8.x4.shared.b16 {%0,%1,%2,%3}, [%4];"
                         : "=r"(a0), "=r"(a1), "=r"(a2), "=r"(a3) : "r"(addr));
        }
        unsigned b[8];
#pragma unroll
        for (int h = 0; h < 2; ++h) {   // two x4.trans loads cover n0+0..15, n0+16..31
            int nb = n0 + h * 16;
            unsigned addr = sa(&ws[kk * 16 + (lane & 7) + ((lane >> 3) & 1) * 8]
                                 [nb + (lane >> 4) * 8]);
            asm volatile("ldmatrix.sync.aligned.m8n8.x4.trans.shared.b16 {%0,%1,%2,%3}, [%4];"
                         : "=r"(b[h * 4]), "=r"(b[h * 4 + 1]), "=r"(b[h * 4 + 2]), "=r"(b[h * 4 + 3])
                         : "r"(addr));
        }
        // n8 tiles: 0 -> {b0,b1}, 1 -> {b2,b3}, 2 -> {b4,b5}, 3 -> {b6,b7}
#pragma unroll
        for (int nt = 0; nt < 4; ++nt) {
            asm volatile(
                "mma.sync.aligned.m16n8k16.row.col.f32.f16.f16.f32 "
                "{%0,%1,%2,%3}, {%4,%5,%6,%7}, {%8,%9}, {%0,%1,%2,%3};"
                : "+f"(c[nt][0]), "+f"(c[nt][1]), "+f"(c[nt][2]), "+f"(c[nt][3])
                : "r"(a0), "r"(a1), "r"(a2), "r"(a3),
                  "r"(b[nt * 2]), "r"(b[nt * 2 + 1]));
        }
    }

    // epilogue: write fp16 H. acc layout: lane -> rows m0+(lane>>2), +8; cols nt*8+(lane&3)*2
    int rA = rbase + m0 + (lane >> 2);
    int rB = rA + 8;
#pragma unroll
    for (int nt = 0; nt < 4; ++nt) {
        int ch2 = ((n0 + nt * 8) >> 1) + (lane & 3);   // half2 column index
        if (rA < NN) g_h2[rA * 32 + ch2] = __floats2half2_rn(c[nt][0], c[nt][1]);
        if (rB < NN) g_h2[rB * 32 + ch2] = __floats2half2_rn(c[nt][2], c[nt][3]);
    }
}

// ---------------------------------------------------------------------------
// gather-aggregate (fp16 rows, fp32 accumulate): one warp per node.
// mode 0: write fp16 to dst (1=g_xh1, 2=g_xh2). mode 1: fused final projection.
__global__ void __launch_bounds__(256) agg_k(const float* __restrict__ bias,
                                             int dst, int mode,
                                             const float* __restrict__ Wf,
                                             const float* __restrict__ bf,
                                             float* __restrict__ out) {
    int node = blockIdx.x * 8 + (threadIdx.x >> 5);   // grid = NN/8 exactly
    int lane = threadIdx.x & 31;

    const __half2* H2 = g_h2;
    float sn = g_selfnorm[node];
    float2 hv = __half22float2(H2[node * 32 + lane]);
    float ax = hv.x * sn, ay = hv.y * sn;

    int p = g_off[node], e = g_off[node + 1];
    for (; p + 3 < e; p += 4) {
        int2 e1 = g_edge[p];
        int2 e2 = g_edge[p + 1];
        int2 e3 = g_edge[p + 2];
        int2 e4 = g_edge[p + 3];
        float2 a = __half22float2(H2[e1.x * 32 + lane]);
        float2 b = __half22float2(H2[e2.x * 32 + lane]);
        float2 c = __half22float2(H2[e3.x * 32 + lane]);
        float2 d = __half22float2(H2[e4.x * 32 + lane]);
        float n1 = __int_as_float(e1.y), n2 = __int_as_float(e2.y);
        float n3 = __int_as_float(e3.y), n4 = __int_as_float(e4.y);
        ax += a.x * n1 + b.x * n2 + c.x * n3 + d.x * n4;
        ay += a.y * n1 + b.y * n2 + c.y * n3 + d.y * n4;
    }
    for (; p < e; ++p) {
        int2 e1 = g_edge[p];
        float n1 = __int_as_float(e1.y);
        float2 a = __half22float2(H2[e1.x * 32 + lane]);
        ax += a.x * n1;
        ay += a.y * n1;
    }

    float o0 = fmaxf(ax + bias[lane * 2    ], 0.f);
    float o1 = fmaxf(ay + bias[lane * 2 + 1], 0.f);

    if (mode == 0) {
        __half2* Y = (dst == 1) ? g_xh1 : g_xh2;
        Y[node * 32 + lane] = __floats2half2_rn(o0, o1);
    } else {
        float a = o0 * Wf[lane * 2] + o1 * Wf[lane * 2 + 1];
#pragma unroll
        for (int o = 16; o; o >>= 1) a += __shfl_down_sync(0xffffffffu, a, o);
        if (lane == 0) out[node] = a + bf[0];
    }
}

// ---------------------------------------------------------------------------
extern "C" void kernel_launch(void* const* d_in, const int* in_sizes, int n_in,
                              void* d_out, int out_size) {
    const float* x  = (const float*)d_in[0];
    const int*   ei = (const int*)d_in[1];      // [2, E] (int32 on device)
    const float* ew = (const float*)d_in[2];
    const float* Ws = (const float*)d_in[3];    // [L, 64, 64]
    const float* bs = (const float*)d_in[4];    // [L, 64]
    const float* Wf = (const float*)d_in[5];    // [64, 1]
    const float* bf = (const float*)d_in[6];    // [1]
    float*       out = (float*)d_out;
    // d_in[7] = prob (unused, dropout p=0)

    const int* erow = ei;        // sources (x_j)
    const int* ecol = ei + EE;   // targets (aggregation)

    const int TB = 256;
    const int E4 = EE / 4;
    // graph normalization + CSR build (once, reused by all layers)
    init_k    <<<(NN + TB - 1) / TB, TB>>>();
    deg_k     <<<(E4 + TB - 1) / TB, TB>>>(ecol, ew);
    dis_scan_a<<<NBLK, SCAN_B>>>();
    scan_c    <<<NBLK, SCAN_B>>>();
    scatter_k <<<(E4 + TB - 1) / TB, TB>>>(erow, ecol, ew);

    // layer 0: x -> g_h2 -> g_xh1
    gemm_k<<<(NN + 63) / 64, 256>>>(x, 0, Ws + 0 * DD * DD);
    agg_k <<<NN / 8, 256>>>(bs + 0 * DD, 1, 0, Wf, bf, out);
    // layer 1: g_xh1 -> g_h2 -> g_xh2
    gemm_k<<<(NN + 63) / 64, 256>>>(x, 1, Ws + 1 * DD * DD);
    agg_k <<<NN / 8, 256>>>(bs + 1 * DD, 2, 0, Wf, bf, out);
    // layer 2: g_xh2 -> g_h2 -> out (fused final projection)
    gemm_k<<<(NN + 63) / 64, 256>>>(x, 2, Ws + 2 * DD * DD);
    agg_k <<<NN / 8, 256>>>(bs + 2 * DD, 0, 1, Wf, bf, out);
}

// round 9
// speedup vs baseline: 1.7999x; 1.0669x over previous
#include <cuda_runtime.h>
#include <cuda_fp16.h>

#define NN 50000
#define EE 1250000
#define DD 64
#define LL 3
#define SCAN_B 256
#define NBLK ((NN + SCAN_B - 1) / SCAN_B)   // 196

// ---- scratch (static device allocations; referenced ONLY from device code) ----
// NOTE: g_deg / g_indeg start zeroed (BSS) and are re-zeroed by scatter_k each
// call, so every graph replay sees identical state.
__device__ float g_deg[NN];
__device__ float g_dis[NN];
__device__ int   g_indeg[NN];
__device__ int   g_off[NN + 1];
__device__ int   g_cur[NN];
__device__ int   g_bsum[NBLK];
__device__ __align__(16) int2    g_edge[EE];       // {src_row, weight bits}
__device__ __align__(16) __half2 g_h2 [NN * 32];   // Hs = dis[r]*H[r]  (fp16)
__device__ __align__(16) __half2 g_xh1[NN * 32];   // activations fp16
__device__ __align__(16) __half2 g_xh2[NN * 32];

__device__ __forceinline__ unsigned sa(const void* p) {
    return (unsigned)__cvta_generic_to_shared(p);
}

// ---------------------------------------------------------------------------
// 1) accumulate weighted degree + in-degree (4 edges/thread, vector reads)
__global__ void deg_k(const int* __restrict__ col,
                      const float* __restrict__ w) {
    int i = blockIdx.x * blockDim.x + threadIdx.x;   // i < EE/4
    if (i < EE / 4) {
        int4   c4 = ((const int4*)col)[i];
        float4 w4 = ((const float4*)w)[i];
        atomicAdd(&g_deg[c4.x], w4.x); atomicAdd(&g_indeg[c4.x], 1);
        atomicAdd(&g_deg[c4.y], w4.y); atomicAdd(&g_indeg[c4.y], 1);
        atomicAdd(&g_deg[c4.z], w4.z); atomicAdd(&g_indeg[c4.z], 1);
        atomicAdd(&g_deg[c4.w], w4.w); atomicAdd(&g_indeg[c4.w], 1);
    }
}

// 2) dis = (deg + 2)^{-1/2}  + per-block indeg sums (merged)
__global__ void dis_scan_a() {
    __shared__ int s[SCAN_B];
    int t = threadIdx.x;
    int i = blockIdx.x * SCAN_B + t;
    int v = 0;
    if (i < NN) {
        g_dis[i] = rsqrtf(g_deg[i] + 2.0f);   // self-loop fill folded in
        v = g_indeg[i];
    }
    s[t] = v;
    __syncthreads();
#pragma unroll
    for (int off = SCAN_B / 2; off > 0; off >>= 1) {
        if (t < off) s[t] += s[t + off];
        __syncthreads();
    }
    if (t == 0) g_bsum[blockIdx.x] = s[0];
}

// 3) per-block exclusive scan; block prefix computed inline from g_bsum
__global__ void scan_c() {
    __shared__ int s[SCAN_B];
    __shared__ int bpre;
    int t = threadIdx.x;

    int pv = (t < NBLK && t < blockIdx.x) ? g_bsum[t] : 0;
    s[t] = pv;
    __syncthreads();
#pragma unroll
    for (int off = SCAN_B / 2; off > 0; off >>= 1) {
        if (t < off) s[t] += s[t + off];
        __syncthreads();
    }
    if (t == 0) bpre = s[0];
    __syncthreads();

    int i = blockIdx.x * SCAN_B + t;
    int v = (i < NN) ? g_indeg[i] : 0;
    s[t] = v;
    __syncthreads();
    for (int off = 1; off < SCAN_B; off <<= 1) {
        int u = (t >= off) ? s[t - off] : 0;
        __syncthreads();
        s[t] += u;
        __syncthreads();
    }
    if (i < NN) {
        int excl = s[t] - v + bpre;
        g_off[i] = excl;
        g_cur[i] = excl;
    }
    if (blockIdx.x == 0 && t == 0) g_off[NN] = EE;
}

// 4) scatter 4 edges/thread into CSR ({row, weight}); re-zero deg/indeg for
//    the next graph replay (all consumers of deg/indeg already ran).
__global__ void scatter_k(const int* __restrict__ row,
                          const int* __restrict__ col,
                          const float* __restrict__ w) {
    int i = blockIdx.x * blockDim.x + threadIdx.x;
    if (i < EE / 4) {
        int4   r4 = ((const int4*)row)[i];
        int4   c4 = ((const int4*)col)[i];
        float4 w4 = ((const float4*)w)[i];
        int p;
        p = atomicAdd(&g_cur[c4.x], 1); g_edge[p] = make_int2(r4.x, __float_as_int(w4.x));
        p = atomicAdd(&g_cur[c4.y], 1); g_edge[p] = make_int2(r4.y, __float_as_int(w4.y));
        p = atomicAdd(&g_cur[c4.z], 1); g_edge[p] = make_int2(r4.z, __float_as_int(w4.z));
        p = atomicAdd(&g_cur[c4.w], 1); g_edge[p] = make_int2(r4.w, __float_as_int(w4.w));
    }
    if (i < NN / 4) {
        ((float4*)g_deg)[i] = make_float4(0.f, 0.f, 0.f, 0.f);
        ((int4*)g_indeg)[i] = make_int4(0, 0, 0, 0);
    }
}

// ---------------------------------------------------------------------------
// Hs = dis[row] * (X @ W), fp16 tensor-core GEMM (m16n8k16, fp32 accum).
// CTA: 64x64, K=64. 8 warps: warp_m = wid%4 (16 rows), warp_n = wid/4 (32 cols).
// src: 0 = fp32 xin, 1 = g_xh1, 2 = g_xh2.
__global__ void __launch_bounds__(256) gemm_k(const float* __restrict__ xin,
                                              int src,
                                              const float* __restrict__ W) {
    __shared__ __half xs[64][72];   // X tile  (pad 72: row 144B, 16B-aligned)
    __shared__ __half ws[64][72];   // W[k][n]
    int tid = threadIdx.x;
    int rbase = blockIdx.x * 64;

    // stage W: fp32 -> fp16
    {
        const float4* W4 = (const float4*)W;
#pragma unroll
        for (int i = 0; i < 4; ++i) {
            int idx4 = tid + i * 256;          // 0..1023
            int r = idx4 >> 4, q = idx4 & 15;
            float4 v = W4[idx4];
            *(__half2*)&ws[r][q * 4]     = __floats2half2_rn(v.x, v.y);
            *(__half2*)&ws[r][q * 4 + 2] = __floats2half2_rn(v.z, v.w);
        }
    }

    // stage X tile
    if (src == 0) {
        const float4* X4 = (const float4*)xin;
#pragma unroll
        for (int i = 0; i < 4; ++i) {
            int idx4 = tid + i * 256;
            int r = idx4 >> 4, q = idx4 & 15;
            int gr = rbase + r;
            float4 v = (gr < NN) ? X4[gr * 16 + q] : make_float4(0.f, 0.f, 0.f, 0.f);
            *(__half2*)&xs[r][q * 4]     = __floats2half2_rn(v.x, v.y);
            *(__half2*)&xs[r][q * 4 + 2] = __floats2half2_rn(v.z, v.w);
        }
    } else {
        const uint4* Xh = (const uint4*)((src == 1) ? g_xh1 : g_xh2); // 8 uint4/row
#pragma unroll
        for (int i = 0; i < 2; ++i) {
            int idx = tid + i * 256;           // 0..511
            int r = idx >> 3, q = idx & 7;
            int gr = rbase + r;
            uint4 v = (gr < NN) ? Xh[gr * 8 + q] : make_uint4(0u, 0u, 0u, 0u);
            *(uint4*)&xs[r][q * 8] = v;
        }
    }
    __syncthreads();

    int wid  = tid >> 5, lane = tid & 31;
    int m0 = (wid & 3) * 16;          // warp row base
    int n0 = (wid >> 2) * 32;         // warp col base

    float c[4][4] = {};
#pragma unroll
    for (int kk = 0; kk < 4; ++kk) {
        unsigned a0, a1, a2, a3;
        {
            unsigned addr = sa(&xs[m0 + (lane & 15)][kk * 16 + (lane >> 4) * 8]);
            asm volatile("ldmatrix.sync.aligned.m8n8.x4.shared.b16 {%0,%1,%2,%3}, [%4];"
                         : "=r"(a0), "=r"(a1), "=r"(a2), "=r"(a3) : "r"(addr));
        }
        unsigned b[8];
#pragma unroll
        for (int h = 0; h < 2; ++h) {
            int nb = n0 + h * 16;
            unsigned addr = sa(&ws[kk * 16 + (lane & 7) + ((lane >> 3) & 1) * 8]
                                 [nb + (lane >> 4) * 8]);
            asm volatile("ldmatrix.sync.aligned.m8n8.x4.trans.shared.b16 {%0,%1,%2,%3}, [%4];"
                         : "=r"(b[h * 4]), "=r"(b[h * 4 + 1]), "=r"(b[h * 4 + 2]), "=r"(b[h * 4 + 3])
                         : "r"(addr));
        }
#pragma unroll
        for (int nt = 0; nt < 4; ++nt) {
            asm volatile(
                "mma.sync.aligned.m16n8k16.row.col.f32.f16.f16.f32 "
                "{%0,%1,%2,%3}, {%4,%5,%6,%7}, {%8,%9}, {%0,%1,%2,%3};"
                : "+f"(c[nt][0]), "+f"(c[nt][1]), "+f"(c[nt][2]), "+f"(c[nt][3])
                : "r"(a0), "r"(a1), "r"(a2), "r"(a3),
                  "r"(b[nt * 2]), "r"(b[nt * 2 + 1]));
        }
    }

    // epilogue: Hs = dis[row] * acc, fp16.
    // acc layout: rows m0+(lane>>2), +8; cols nt*8+(lane&3)*2
    int rA = rbase + m0 + (lane >> 2);
    int rB = rA + 8;
    float dA = (rA < NN) ? g_dis[rA] : 0.f;
    float dB = (rB < NN) ? g_dis[rB] : 0.f;
#pragma unroll
    for (int nt = 0; nt < 4; ++nt) {
        int ch2 = ((n0 + nt * 8) >> 1) + (lane & 3);
        if (rA < NN) g_h2[rA * 32 + ch2] = __floats2half2_rn(c[nt][0] * dA, c[nt][1] * dA);
        if (rB < NN) g_h2[rB * 32 + ch2] = __floats2half2_rn(c[nt][2] * dB, c[nt][3] * dB);
    }
}

// ---------------------------------------------------------------------------
// gather-aggregate: agg = dis[c] * (sum_e w_e*Hs[r_e] + 2*Hs[c]); relu(+bias).
// mode 0: write fp16 to dst (1=g_xh1, 2=g_xh2). mode 1: fused final projection.
__global__ void __launch_bounds__(256) agg_k(const float* __restrict__ bias,
                                             int dst, int mode,
                                             const float* __restrict__ Wf,
                                             const float* __restrict__ bf,
                                             float* __restrict__ out) {
    int node = blockIdx.x * 8 + (threadIdx.x >> 5);   // grid = NN/8 exactly
    int lane = threadIdx.x & 31;

    const __half2* H2 = g_h2;
    float2 hv = __half22float2(H2[node * 32 + lane]);
    float ax = 2.f * hv.x, ay = 2.f * hv.y;

    int p = g_off[node], e = g_off[node + 1];
    for (; p + 3 < e; p += 4) {
        int2 e1 = g_edge[p];
        int2 e2 = g_edge[p + 1];
        int2 e3 = g_edge[p + 2];
        int2 e4 = g_edge[p + 3];
        float2 a = __half22float2(H2[e1.x * 32 + lane]);
        float2 b = __half22float2(H2[e2.x * 32 + lane]);
        float2 c = __half22float2(H2[e3.x * 32 + lane]);
        float2 d = __half22float2(H2[e4.x * 32 + lane]);
        float n1 = __int_as_float(e1.y), n2 = __int_as_float(e2.y);
        float n3 = __int_as_float(e3.y), n4 = __int_as_float(e4.y);
        ax += a.x * n1 + b.x * n2 + c.x * n3 + d.x * n4;
        ay += a.y * n1 + b.y * n2 + c.y * n3 + d.y * n4;
    }
    for (; p < e; ++p) {
        int2 e1 = g_edge[p];
        float n1 = __int_as_float(e1.y);
        float2 a = __half22float2(H2[e1.x * 32 + lane]);
        ax += a.x * n1;
        ay += a.y * n1;
    }

    float dc = g_dis[node];
    float o0 = fmaxf(ax * dc + bias[lane * 2    ], 0.f);
    float o1 = fmaxf(ay * dc + bias[lane * 2 + 1], 0.f);

    if (mode == 0) {
        __half2* Y = (dst == 1) ? g_xh1 : g_xh2;
        Y[node * 32 + lane] = __floats2half2_rn(o0, o1);
    } else {
        float a = o0 * Wf[lane * 2] + o1 * Wf[lane * 2 + 1];
#pragma unroll
        for (int o = 16; o; o >>= 1) a += __shfl_down_sync(0xffffffffu, a, o);
        if (lane == 0) out[node] = a + bf[0];
    }
}

// ---------------------------------------------------------------------------
extern "C" void kernel_launch(void* const* d_in, const int* in_sizes, int n_in,
                              void* d_out, int out_size) {
    const float* x  = (const float*)d_in[0];
    const int*   ei = (const int*)d_in[1];      // [2, E] (int32 on device)
    const float* ew = (const float*)d_in[2];
    const float* Ws = (const float*)d_in[3];    // [L, 64, 64]
    const float* bs = (const float*)d_in[4];    // [L, 64]
    const float* Wf = (const float*)d_in[5];    // [64, 1]
    const float* bf = (const float*)d_in[6];    // [1]
    float*       out = (float*)d_out;
    // d_in[7] = prob (unused, dropout p=0)

    const int* erow = ei;        // sources (x_j)
    const int* ecol = ei + EE;   // targets (aggregation)

    const int TB = 256;
    const int E4 = EE / 4;
    // graph normalization + CSR build (once, reused by all layers)
    deg_k     <<<(E4 + TB - 1) / TB, TB>>>(ecol, ew);        // launch 1
    dis_scan_a<<<NBLK, SCAN_B>>>();                          // launch 2
    scan_c    <<<NBLK, SCAN_B>>>();                          // launch 3
    scatter_k <<<(E4 + TB - 1) / TB, TB>>>(erow, ecol, ew);  // launch 4

    // layer 0: x -> g_h2 -> g_xh1
    gemm_k<<<(NN + 63) / 64, 256>>>(x, 0, Ws + 0 * DD * DD); // launch 5
    agg_k <<<NN / 8, 256>>>(bs + 0 * DD, 1, 0, Wf, bf, out); // launch 6 (ncu window)
    // layer 1: g_xh1 -> g_h2 -> g_xh2
    gemm_k<<<(NN + 63) / 64, 256>>>(x, 1, Ws + 1 * DD * DD);
    agg_k <<<NN / 8, 256>>>(bs + 1 * DD, 2, 0, Wf, bf, out);
    // layer 2: g_xh2 -> g_h2 -> out (fused final projection)
    gemm_k<<<(NN + 63) / 64, 256>>>(x, 2, Ws + 2 * DD * DD);
    agg_k <<<NN / 8, 256>>>(bs + 2 * DD, 0, 1, Wf, bf, out);
}

// round 11
// speedup vs baseline: 1.8589x; 1.0328x over previous
#include <cuda_runtime.h>
#include <cuda_fp16.h>

#define NN 50000
#define EE 1250000
#define DD 64
#define LL 3
#define SCAN_B 256
#define NBLK ((NN + SCAN_B - 1) / SCAN_B)   // 196

// ---- scratch (static device allocations; referenced ONLY from device code) ----
// g_indeg starts zeroed (BSS) and is re-zeroed by scatter_k each call, so every
// graph replay sees identical state.
__device__ int   g_indeg[NN];
__device__ float g_dis[NN];
__device__ int   g_off[NN + 1];
__device__ int   g_bsum[NBLK];
__device__ __align__(16) int   g_rank[EE];       // rank of edge within its dest segment
__device__ __align__(16) int2  g_edge[EE];       // {src_row, weight bits}
__device__ __align__(16) __half2 g_h2 [NN * 32]; // Hs = dis[r]*H[r]  (fp16)
__device__ __align__(16) __half2 g_xh1[NN * 32]; // activations fp16
__device__ __align__(16) __half2 g_xh2[NN * 32];

__device__ __forceinline__ unsigned sa(const void* p) {
    return (unsigned)__cvta_generic_to_shared(p);
}

// ---------------------------------------------------------------------------
// 1) count in-degree; the atomic's return value IS the edge's segment rank.
__global__ void count_k(const int* __restrict__ col) {
    int i = blockIdx.x * blockDim.x + threadIdx.x;   // i < EE/4
    if (i < EE / 4) {
        int4 c4 = ((const int4*)col)[i];
        int r0 = atomicAdd(&g_indeg[c4.x], 1);
        int r1 = atomicAdd(&g_indeg[c4.y], 1);
        int r2 = atomicAdd(&g_indeg[c4.z], 1);
        int r3 = atomicAdd(&g_indeg[c4.w], 1);
        ((int4*)g_rank)[i] = make_int4(r0, r1, r2, r3);
    }
}

// 2a) per-block indeg sums
__global__ void scan_a() {
    __shared__ int s[SCAN_B];
    int t = threadIdx.x;
    int i = blockIdx.x * SCAN_B + t;
    s[t] = (i < NN) ? g_indeg[i] : 0;
    __syncthreads();
#pragma unroll
    for (int off = SCAN_B / 2; off > 0; off >>= 1) {
        if (t < off) s[t] += s[t + off];
        __syncthreads();
    }
    if (t == 0) g_bsum[blockIdx.x] = s[0];
}

// 2b) per-block exclusive scan; block prefix computed inline from g_bsum
__global__ void scan_c() {
    __shared__ int s[SCAN_B];
    __shared__ int bpre;
    int t = threadIdx.x;

    int pv = (t < NBLK && t < blockIdx.x) ? g_bsum[t] : 0;
    s[t] = pv;
    __syncthreads();
#pragma unroll
    for (int off = SCAN_B / 2; off > 0; off >>= 1) {
        if (t < off) s[t] += s[t + off];
        __syncthreads();
    }
    if (t == 0) bpre = s[0];
    __syncthreads();

    int i = blockIdx.x * SCAN_B + t;
    int v = (i < NN) ? g_indeg[i] : 0;
    s[t] = v;
    __syncthreads();
    for (int off = 1; off < SCAN_B; off <<= 1) {
        int u = (t >= off) ? s[t - off] : 0;
        __syncthreads();
        s[t] += u;
        __syncthreads();
    }
    if (i < NN) g_off[i] = s[t] - v + bpre;
    if (blockIdx.x == 0 && t == 0) g_off[NN] = EE;
}

// 3) atomic-free scatter: p = off[c] + rank[e]. Re-zero indeg for next replay.
__global__ void scatter_k(const int* __restrict__ row,
                          const int* __restrict__ col,
                          const float* __restrict__ w) {
    int i = blockIdx.x * blockDim.x + threadIdx.x;
    if (i < EE / 4) {
        int4   r4 = ((const int4*)row)[i];
        int4   c4 = ((const int4*)col)[i];
        float4 w4 = ((const float4*)w)[i];
        int4   k4 = ((const int4*)g_rank)[i];
        g_edge[g_off[c4.x] + k4.x] = make_int2(r4.x, __float_as_int(w4.x));
        g_edge[g_off[c4.y] + k4.y] = make_int2(r4.y, __float_as_int(w4.y));
        g_edge[g_off[c4.z] + k4.z] = make_int2(r4.z, __float_as_int(w4.z));
        g_edge[g_off[c4.w] + k4.w] = make_int2(r4.w, __float_as_int(w4.w));
    }
    if (i < NN / 4) ((int4*)g_indeg)[i] = make_int4(0, 0, 0, 0);
}

// 4) weighted degree via coalesced segmented sum; dis = rsqrt(deg + 2)
__global__ void __launch_bounds__(256) disseg_k() {
    int node = blockIdx.x * 8 + (threadIdx.x >> 5);   // grid = NN/8 exactly
    int lane = threadIdx.x & 31;
    int s = g_off[node], e = g_off[node + 1];
    float sum = 0.f;
    for (int p = s + lane; p < e; p += 32)
        sum += __int_as_float(g_edge[p].y);
#pragma unroll
    for (int o = 16; o; o >>= 1) sum += __shfl_down_sync(0xffffffffu, sum, o);
    if (lane == 0) g_dis[node] = rsqrtf(sum + 2.0f);
}

// ---------------------------------------------------------------------------
// Hs = dis[row] * (X @ W), fp16 tensor-core GEMM (m16n8k16, fp32 accum).
// CTA: 64x64, K=64. 8 warps: warp_m = wid%4 (16 rows), warp_n = wid/4 (32 cols).
// src: 0 = fp32 xin, 1 = g_xh1, 2 = g_xh2.
__global__ void __launch_bounds__(256) gemm_k(const float* __restrict__ xin,
                                              int src,
                                              const float* __restrict__ W) {
    __shared__ __half xs[64][72];   // X tile  (pad 72: row 144B, 16B-aligned)
    __shared__ __half ws[64][72];   // W[k][n]
    int tid = threadIdx.x;
    int rbase = blockIdx.x * 64;

    // stage W: fp32 -> fp16
    {
        const float4* W4 = (const float4*)W;
#pragma unroll
        for (int i = 0; i < 4; ++i) {
            int idx4 = tid + i * 256;          // 0..1023
            int r = idx4 >> 4, q = idx4 & 15;
            float4 v = W4[idx4];
            *(__half2*)&ws[r][q * 4]     = __floats2half2_rn(v.x, v.y);
            *(__half2*)&ws[r][q * 4 + 2] = __floats2half2_rn(v.z, v.w);
        }
    }

    // stage X tile
    if (src == 0) {
        const float4* X4 = (const float4*)xin;
#pragma unroll
        for (int i = 0; i < 4; ++i) {
            int idx4 = tid + i * 256;
            int r = idx4 >> 4, q = idx4 & 15;
            int gr = rbase + r;
            float4 v = (gr < NN) ? X4[gr * 16 + q] : make_float4(0.f, 0.f, 0.f, 0.f);
            *(__half2*)&xs[r][q * 4]     = __floats2half2_rn(v.x, v.y);
            *(__half2*)&xs[r][q * 4 + 2] = __floats2half2_rn(v.z, v.w);
        }
    } else {
        const uint4* Xh = (const uint4*)((src == 1) ? g_xh1 : g_xh2); // 8 uint4/row
#pragma unroll
        for (int i = 0; i < 2; ++i) {
            int idx = tid + i * 256;           // 0..511
            int r = idx >> 3, q = idx & 7;
            int gr = rbase + r;
            uint4 v = (gr < NN) ? Xh[gr * 8 + q] : make_uint4(0u, 0u, 0u, 0u);
            *(uint4*)&xs[r][q * 8] = v;
        }
    }
    __syncthreads();

    int wid  = tid >> 5, lane = tid & 31;
    int m0 = (wid & 3) * 16;          // warp row base
    int n0 = (wid >> 2) * 32;         // warp col base

    float c[4][4] = {};
#pragma unroll
    for (int kk = 0; kk < 4; ++kk) {
        unsigned a0, a1, a2, a3;
        {
            unsigned addr = sa(&xs[m0 + (lane & 15)][kk * 16 + (lane >> 4) * 8]);
            asm volatile("ldmatrix.sync.aligned.m8n8.x4.shared.b16 {%0,%1,%2,%3}, [%4];"
                         : "=r"(a0), "=r"(a1), "=r"(a2), "=r"(a3) : "r"(addr));
        }
        unsigned b[8];
#pragma unroll
        for (int h = 0; h < 2; ++h) {
            int nb = n0 + h * 16;
            unsigned addr = sa(&ws[kk * 16 + (lane & 7) + ((lane >> 3) & 1) * 8]
                                 [nb + (lane >> 4) * 8]);
            asm volatile("ldmatrix.sync.aligned.m8n8.x4.trans.shared.b16 {%0,%1,%2,%3}, [%4];"
                         : "=r"(b[h * 4]), "=r"(b[h * 4 + 1]), "=r"(b[h * 4 + 2]), "=r"(b[h * 4 + 3])
                         : "r"(addr));
        }
#pragma unroll
        for (int nt = 0; nt < 4; ++nt) {
            asm volatile(
                "mma.sync.aligned.m16n8k16.row.col.f32.f16.f16.f32 "
                "{%0,%1,%2,%3}, {%4,%5,%6,%7}, {%8,%9}, {%0,%1,%2,%3};"
                : "+f"(c[nt][0]), "+f"(c[nt][1]), "+f"(c[nt][2]), "+f"(c[nt][3])
                : "r"(a0), "r"(a1), "r"(a2), "r"(a3),
                  "r"(b[nt * 2]), "r"(b[nt * 2 + 1]));
        }
    }

    // epilogue: Hs = dis[row] * acc, fp16.
    int rA = rbase + m0 + (lane >> 2);
    int rB = rA + 8;
    float dA = (rA < NN) ? g_dis[rA] : 0.f;
    float dB = (rB < NN) ? g_dis[rB] : 0.f;
#pragma unroll
    for (int nt = 0; nt < 4; ++nt) {
        int ch2 = ((n0 + nt * 8) >> 1) + (lane & 3);
        if (rA < NN) g_h2[rA * 32 + ch2] = __floats2half2_rn(c[nt][0] * dA, c[nt][1] * dA);
        if (rB < NN) g_h2[rB * 32 + ch2] = __floats2half2_rn(c[nt][2] * dB, c[nt][3] * dB);
    }
}

// ---------------------------------------------------------------------------
// gather-aggregate: agg = dis[c] * (sum_e w_e*Hs[r_e] + 2*Hs[c]); relu(+bias).
// mode 0: write fp16 to dst (1=g_xh1, 2=g_xh2). mode 1: fused final projection.
__global__ void __launch_bounds__(256) agg_k(const float* __restrict__ bias,
                                             int dst, int mode,
                                             const float* __restrict__ Wf,
                                             const float* __restrict__ bf,
                                             float* __restrict__ out) {
    int node = blockIdx.x * 8 + (threadIdx.x >> 5);   // grid = NN/8 exactly
    int lane = threadIdx.x & 31;

    const __half2* H2 = g_h2;
    float2 hv = __half22float2(H2[node * 32 + lane]);
    float ax = 2.f * hv.x, ay = 2.f * hv.y;

    int p = g_off[node], e = g_off[node + 1];
    for (; p + 3 < e; p += 4) {
        int2 e1 = g_edge[p];
        int2 e2 = g_edge[p + 1];
        int2 e3 = g_edge[p + 2];
        int2 e4 = g_edge[p + 3];
        float2 a = __half22float2(H2[e1.x * 32 + lane]);
        float2 b = __half22float2(H2[e2.x * 32 + lane]);
        float2 c = __half22float2(H2[e3.x * 32 + lane]);
        float2 d = __half22float2(H2[e4.x * 32 + lane]);
        float n1 = __int_as_float(e1.y), n2 = __int_as_float(e2.y);
        float n3 = __int_as_float(e3.y), n4 = __int_as_float(e4.y);
        ax += a.x * n1 + b.x * n2 + c.x * n3 + d.x * n4;
        ay += a.y * n1 + b.y * n2 + c.y * n3 + d.y * n4;
    }
    for (; p < e; ++p) {
        int2 e1 = g_edge[p];
        float n1 = __int_as_float(e1.y);
        float2 a = __half22float2(H2[e1.x * 32 + lane]);
        ax += a.x * n1;
        ay += a.y * n1;
    }

    float dc = g_dis[node];
    float o0 = fmaxf(ax * dc + bias[lane * 2    ], 0.f);
    float o1 = fmaxf(ay * dc + bias[lane * 2 + 1], 0.f);

    if (mode == 0) {
        __half2* Y = (dst == 1) ? g_xh1 : g_xh2;
        Y[node * 32 + lane] = __floats2half2_rn(o0, o1);
    } else {
        float a = o0 * Wf[lane * 2] + o1 * Wf[lane * 2 + 1];
#pragma unroll
        for (int o = 16; o; o >>= 1) a += __shfl_down_sync(0xffffffffu, a, o);
        if (lane == 0) out[node] = a + bf[0];
    }
}

// ---------------------------------------------------------------------------
extern "C" void kernel_launch(void* const* d_in, const int* in_sizes, int n_in,
                              void* d_out, int out_size) {
    const float* x  = (const float*)d_in[0];
    const int*   ei = (const int*)d_in[1];      // [2, E] (int32 on device)
    const float* ew = (const float*)d_in[2];
    const float* Ws = (const float*)d_in[3];    // [L, 64, 64]
    const float* bs = (const float*)d_in[4];    // [L, 64]
    const float* Wf = (const float*)d_in[5];    // [64, 1]
    const float* bf = (const float*)d_in[6];    // [1]
    float*       out = (float*)d_out;
    // d_in[7] = prob (unused, dropout p=0)

    const int* erow = ei;        // sources (x_j)
    const int* ecol = ei + EE;   // targets (aggregation)

    const int TB = 256;
    const int E4 = EE / 4;
    // CSR build (once, reused by all layers) — atomic-free scatter via ranks
    count_k  <<<(E4 + TB - 1) / TB, TB>>>(ecol);
    scan_a   <<<NBLK, SCAN_B>>>();
    scan_c   <<<NBLK, SCAN_B>>>();
    scatter_k<<<(E4 + TB - 1) / TB, TB>>>(erow, ecol, ew);
    disseg_k <<<NN / 8, 256>>>();

    // layer 0: x -> g_h2 -> g_xh1
    gemm_k<<<(NN + 63) / 64, 256>>>(x, 0, Ws + 0 * DD * DD);
    agg_k <<<NN / 8, 256>>>(bs + 0 * DD, 1, 0, Wf, bf, out);
    // layer 1: g_xh1 -> g_h2 -> g_xh2
    gemm_k<<<(NN + 63) / 64, 256>>>(x, 1, Ws + 1 * DD * DD);
    agg_k <<<NN / 8, 256>>>(bs + 1 * DD, 2, 0, Wf, bf, out);
    // layer 2: g_xh2 -> g_h2 -> out (fused final projection)
    gemm_k<<<(NN + 63) / 64, 256>>>(x, 2, Ws + 2 * DD * DD);
    agg_k <<<NN / 8, 256>>>(bs + 2 * DD, 0, 1, Wf, bf, out);
}